// round 14
// baseline (speedup 1.0000x reference)
#include <cuda_runtime.h>
#include <cuda_fp16.h>
#include <cstdint>

// SBNet block-sparse 3x3 conv via mma.sync (HMMA) pure-fp16 implicit GEMM.
// R12/R13: fully-unrolled 36-iteration mainloop (address math folded to
// immediates, ptxas cross-iteration LDSM pipelining). Pure fp16 (fp32 accum),
// TPB=448, warp tile M=32 x N=32, SMEM 107.5KB -> 2 CTAs/SM (28 warps).
// x[4][64][448][448] f32, mask[4][1][448][448], weight[64][64][3][3], bias[64],
// out[4][64][448][448]. 14x14 output blocks; active iff max(mask over 16x16
// gather window at offset -1) > 0.5.

namespace {
constexpr int Himg = 448, Wimg = 448, NBLK = 1024, TPB = 448;
constexpr int BS = 14;
constexpr int SM_X = 1024;             // [0..256) bias
constexpr int XB = 256 * 128;          // 256 pixel-rows x 64ch fp16
constexpr int SM_W = SM_X + XB;        // 33792
constexpr int WB = 9 * 64 * 128;       // 9 taps x 64 cout rows x 64 cin fp16
constexpr int SMEM_TOTAL = SM_W + WB;  // 107520
}

__device__ uint16_t g_w[9 * 64 * 64];

__device__ __forceinline__ uint32_t smem_u32(const void* p) {
    uint32_t a;
    asm("{ .reg .u64 t; cvta.to.shared.u64 t, %1; cvt.u32.u64 %0, t; }"
        : "=r"(a) : "l"(p));
    return a;
}
__device__ __forceinline__ void ldsm4(uint32_t* r, uint32_t addr) {
    asm volatile("ldmatrix.sync.aligned.m8n8.x4.shared.b16 {%0,%1,%2,%3}, [%4];"
                 : "=r"(r[0]), "=r"(r[1]), "=r"(r[2]), "=r"(r[3]) : "r"(addr));
}
__device__ __forceinline__ void mma_fp16(float* d, const uint32_t* a,
                                         const uint32_t* b) {
    asm volatile(
        "mma.sync.aligned.m16n8k16.row.col.f32.f16.f16.f32 "
        "{%0,%1,%2,%3},{%4,%5,%6,%7},{%8,%9},{%0,%1,%2,%3};"
        : "+f"(d[0]), "+f"(d[1]), "+f"(d[2]), "+f"(d[3])
        : "r"(a[0]), "r"(a[1]), "r"(a[2]), "r"(a[3]), "r"(b[0]), "r"(b[1]));
}

// one-time: weight[o][c][ky][kx] f32 -> swizzled fp16, layout
// [tap][o-row(128B)][cin], 16B-chunk swizzle: chunk ^= (o&7).
__global__ void wconv_kernel(const float* __restrict__ w) {
    int i = blockIdx.x * blockDim.x + threadIdx.x;
    if (i >= 64 * 64 * 9) return;
    int o = i / 576, r = i - o * 576, c = r / 9, k = r - c * 9;
    uint32_t off16 = k * 4096 + o * 64 + ((((c >> 3) ^ (o & 7)) << 3)) + (c & 7);
    g_w[off16] = __half_as_ushort(__float2half_rn(w[i]));
}

__global__ __launch_bounds__(TPB, 2)
void sbnet_mma_kernel(const float* __restrict__ x,
                      const float* __restrict__ mask,
                      const float* __restrict__ bias,
                      float* __restrict__ out) {
    extern __shared__ char smem[];
    const uint32_t sbase = smem_u32(smem);

    const int b   = blockIdx.x;
    const int n   = b >> 10;
    const int rem = b & (NBLK - 1);
    const int by  = rem >> 5, bx = rem & 31;
    const int t   = threadIdx.x;
    const int wid = t >> 5, lane = t & 31;
    const int y0  = by * BS, x0 = bx * BS;

    // ---- activity: threads 0..255 check the 16x16 gather window ----
    float mv = 0.f;
    if (t < 256) {
        int ty = t >> 4, tx = t & 15;
        int gy = y0 - 1 + ty, gx = x0 - 1 + tx;
        if ((unsigned)gy < (unsigned)Himg && (unsigned)gx < (unsigned)Wimg)
            mv = mask[(size_t)n * Himg * Wimg + gy * Wimg + gx];
    }
    const int act = __syncthreads_or(mv > 0.5f);

    if (!act) {  // zero-fill the 14x14 block for all 64 couts
        for (int i = t; i < 64 * 14 * 7; i += TPB) {
            int co = i / 98, r2 = i - co * 98, y = r2 / 7, j = r2 - y * 7;
            float2* op = (float2*)(out + (((size_t)n * 64 + co) * Himg + y0 + y) * Wimg
                                   + x0 + 2 * j);
            *op = make_float2(0.f, 0.f);
        }
        return;
    }

    // ---- staging: t<256 stage X (64 channels); t>=256 copy W ----
    if (t < 256) {
        if (t < 64) *(float*)(smem + t * 4) = bias[t];
        const int p = t;
        const int ty = p >> 4, tx = p & 15;
        const int gy = y0 - 1 + ty, gx = x0 - 1 + tx;
        const bool inb = (unsigned)gy < (unsigned)Himg && (unsigned)gx < (unsigned)Wimg;
        const float* xp = x + (size_t)n * 64 * Himg * Wimg + (size_t)gy * Wimg + gx;
        const int prow = p * 128, p7 = p & 7;
        #pragma unroll 4
        for (int c = 0; c < 64; c++) {
            float v = inb ? xp[(size_t)c * Himg * Wimg] : 0.f;
            uint32_t off = prow + ((((c >> 3) ^ p7) << 4)) + ((c & 7) << 1);
            *(uint16_t*)(smem + SM_X + off) =
                __half_as_ushort(__float2half_rn(v));
        }
    } else {
        const uint4* sw = (const uint4*)g_w;
        uint4* dw = (uint4*)(smem + SM_W);
        for (int i = t - 256; i < WB / 16; i += 192) dw[i] = sw[i];
    }
    __syncthreads();

    // ---- compute: warp = (mblk 0..6) x (nhalf 0..1); tile M=32, N=32 ----
    const int nhalf = wid / 7;
    const int mblk  = wid - nhalf * 7;
    const int m0 = mblk * 32;              // pixel rows (all valid y<14)
    const int n0 = nhalf * 32;             // cout block
    const int q  = lane >> 2, tq = lane & 3;

    float acc[2][4][4];
    #pragma unroll
    for (int mt = 0; mt < 2; mt++)
        #pragma unroll
        for (int nt = 0; nt < 4; nt++)
            #pragma unroll
            for (int i = 0; i < 4; i++) acc[mt][nt][i] = 0.f;

    // per-lane invariants
    const int arow_l = (lane & 15);        // A: row within m16 tile
    const int ahi    = lane >> 4;          // A: k 16B-chunk select
    const int nrow   = n0 + (lane & 7) + ((lane & 16) >> 1);  // B row (cout)
    const int bhi    = (lane >> 3) & 1;    // B: k 16B-chunk select
    const uint32_t brow = sbase + nrow * 128;  // (nrow+16)&7 == nrow&7
    const int nx7 = nrow & 7;
    const uint32_t abase_r = sbase + (uint32_t)SM_X + (m0 + arow_l) * 128;
    const int ar = m0 + arow_l;

    // ---- fully-unrolled mainloop: 9 taps x 4 k-chunks ----
    #pragma unroll
    for (int tap = 0; tap < 9; tap++) {
        const int ky = tap / 3;                       // compile-time
        const int shift = ky * 16 + (tap - ky * 3);   // compile-time
        const uint32_t ab0 = abase_r + shift * 128;
        const int a70 = (ar + shift) & 7;             // lane-dependent, tap-folded
        const uint32_t wt = (uint32_t)SM_W + tap * 8192;
        #pragma unroll
        for (int kc = 0; kc < 4; kc++) {
            uint32_t ah[2][4], bh[8];
            const uint32_t ch = (((kc * 2 + ahi) ^ a70) << 4);
            ldsm4(ah[0], ab0 + ch);
            ldsm4(ah[1], ab0 + 16 * 128 + ch);
            const uint32_t bha = brow + wt + (((kc * 2 + bhi) ^ nx7) << 4);
            ldsm4(bh + 0, bha);
            ldsm4(bh + 4, bha + 2048);
            // 8 independent MMAs (distinct accumulators)
            #pragma unroll
            for (int mt = 0; mt < 2; mt++)
                #pragma unroll
                for (int nt = 0; nt < 4; nt++)
                    mma_fp16(acc[mt][nt], ah[mt], bh + nt * 2);
        }
    }

    // ---- epilogue: bias + masked stores (y = mblk*2+mt < 14 always) ----
    const float* bias_s = (const float*)smem;
    #pragma unroll
    for (int mt = 0; mt < 2; mt++) {
        const int y = mblk * 2 + mt;
        #pragma unroll
        for (int nt = 0; nt < 4; nt++) {
            const int nb = n0 + nt * 8 + 2 * tq;
            const float b0 = bias_s[nb], b1 = bias_s[nb + 1];
            float* base = out + ((size_t)(n * 64 + nb) * Himg + (y0 + y)) * Wimg + x0;
            base[q] = acc[mt][nt][0] + b0;
            base[(size_t)Himg * Wimg + q] = acc[mt][nt][1] + b1;
            if (q < 6) {
                base[q + 8] = acc[mt][nt][2] + b0;
                base[(size_t)Himg * Wimg + q + 8] = acc[mt][nt][3] + b1;
            }
        }
    }
}

extern "C" void kernel_launch(void* const* d_in, const int* in_sizes, int n_in,
                              void* d_out, int out_size) {
    const float* x      = (const float*)d_in[0];
    const float* mask   = (const float*)d_in[1];
    const float* weight = (const float*)d_in[2];
    const float* bias   = (const float*)d_in[3];
    float* out = (float*)d_out;

    wconv_kernel<<<(64 * 64 * 9 + 255) / 256, 256>>>(weight);

    cudaFuncSetAttribute(sbnet_mma_kernel,
                         cudaFuncAttributeMaxDynamicSharedMemorySize, SMEM_TOTAL);
    sbnet_mma_kernel<<<4 * NBLK, TPB, SMEM_TOTAL>>>(x, mask, bias, out);
}

// round 15
// speedup vs baseline: 1.1282x; 1.1282x over previous
#include <cuda_runtime.h>
#include <cuda_fp16.h>
#include <cstdint>

// SBNet block-sparse 3x3 conv via mma.sync (HMMA) pure-fp16 implicit GEMM.
// R14: persistent CTAs (grid = 2*148) — W (73KB) + bias staged into smem ONCE
// per CTA, then loop over blocks with stride gridDim.x. Mainloop = R12 config
// (tap loop rolled, kc unrolled; no spills). Pure fp16, fp32 accumulate.
// TPB=448, warp tile M=32 x N=32, SMEM 107.5KB -> 2 CTAs/SM (28 warps).
// x[4][64][448][448] f32, mask[4][1][448][448], weight[64][64][3][3], bias[64],
// out[4][64][448][448]. 14x14 output blocks; active iff max(mask over 16x16
// gather window at offset -1) > 0.5.

namespace {
constexpr int Himg = 448, Wimg = 448, TPB = 448;
constexpr int BS = 14;
constexpr int NBLK_TOTAL = 4 * 1024;   // 4 images x 32x32 blocks
constexpr int GRID = 2 * 148;          // persistent: 2 CTAs per SM
constexpr int SM_X = 1024;             // [0..256) bias
constexpr int XB = 256 * 128;          // 256 pixel-rows x 64ch fp16
constexpr int SM_W = SM_X + XB;        // 33792
constexpr int WB = 9 * 64 * 128;       // 9 taps x 64 cout rows x 64 cin fp16
constexpr int SMEM_TOTAL = SM_W + WB;  // 107520
}

__device__ uint16_t g_w[9 * 64 * 64];

__device__ __forceinline__ uint32_t smem_u32(const void* p) {
    uint32_t a;
    asm("{ .reg .u64 t; cvta.to.shared.u64 t, %1; cvt.u32.u64 %0, t; }"
        : "=r"(a) : "l"(p));
    return a;
}
__device__ __forceinline__ void ldsm4(uint32_t* r, uint32_t addr) {
    asm volatile("ldmatrix.sync.aligned.m8n8.x4.shared.b16 {%0,%1,%2,%3}, [%4];"
                 : "=r"(r[0]), "=r"(r[1]), "=r"(r[2]), "=r"(r[3]) : "r"(addr));
}
__device__ __forceinline__ void mma_fp16(float* d, const uint32_t* a,
                                         const uint32_t* b) {
    asm volatile(
        "mma.sync.aligned.m16n8k16.row.col.f32.f16.f16.f32 "
        "{%0,%1,%2,%3},{%4,%5,%6,%7},{%8,%9},{%0,%1,%2,%3};"
        : "+f"(d[0]), "+f"(d[1]), "+f"(d[2]), "+f"(d[3])
        : "r"(a[0]), "r"(a[1]), "r"(a[2]), "r"(a[3]), "r"(b[0]), "r"(b[1]));
}

// one-time: weight[o][c][ky][kx] f32 -> swizzled fp16, layout
// [tap][o-row(128B)][cin], 16B-chunk swizzle: chunk ^= (o&7).
__global__ void wconv_kernel(const float* __restrict__ w) {
    int i = blockIdx.x * blockDim.x + threadIdx.x;
    if (i >= 64 * 64 * 9) return;
    int o = i / 576, r = i - o * 576, c = r / 9, k = r - c * 9;
    uint32_t off16 = k * 4096 + o * 64 + ((((c >> 3) ^ (o & 7)) << 3)) + (c & 7);
    g_w[off16] = __half_as_ushort(__float2half_rn(w[i]));
}

__global__ __launch_bounds__(TPB, 2)
void sbnet_mma_kernel(const float* __restrict__ x,
                      const float* __restrict__ mask,
                      const float* __restrict__ bias,
                      float* __restrict__ out) {
    extern __shared__ char smem[];
    const uint32_t sbase = smem_u32(smem);

    const int t   = threadIdx.x;
    const int wid = t >> 5, lane = t & 31;

    // ---- one-time staging: W image + bias (all 448 threads) ----
    {
        const uint4* sw = (const uint4*)g_w;
        uint4* dw = (uint4*)(smem + SM_W);
        for (int i = t; i < WB / 16; i += TPB) dw[i] = sw[i];
        if (t < 64) *(float*)(smem + t * 4) = bias[t];
        // ordered before first mainloop read by the __syncthreads_or below
    }

    // per-lane invariants (block-independent)
    const int nhalf = wid / 7;
    const int mblk  = wid - nhalf * 7;
    const int m0 = mblk * 32;              // pixel rows (all valid y<14)
    const int n0 = nhalf * 32;             // cout block
    const int q  = lane >> 2, tq = lane & 3;
    const int arow_l = (lane & 15);        // A: row within m16 tile
    const int ahi    = lane >> 4;          // A: k 16B-chunk select
    const int nrow   = n0 + (lane & 7) + ((lane & 16) >> 1);  // B row (cout)
    const int bhi    = (lane >> 3) & 1;    // B: k 16B-chunk select
    const uint32_t brow = sbase + nrow * 128;  // (nrow+16)&7 == nrow&7
    const int nx7 = nrow & 7;
    const int ar = m0 + arow_l;
    const uint32_t abase_r = sbase + (uint32_t)SM_X + ar * 128;
    const float* bias_s = (const float*)smem;

    // ---- persistent loop over blocks ----
    for (int blk = blockIdx.x; blk < NBLK_TOTAL; blk += GRID) {
        const int n   = blk >> 10;
        const int rem = blk & 1023;
        const int by  = rem >> 5, bx = rem & 31;
        const int y0  = by * BS, x0 = bx * BS;

        // activity: threads 0..255 check the 16x16 gather window.
        // __syncthreads_or is also the barrier that orders the previous
        // iteration's X reads (mainloop) before this iteration's X writes.
        float mv = 0.f;
        if (t < 256) {
            int ty = t >> 4, tx = t & 15;
            int gy = y0 - 1 + ty, gx = x0 - 1 + tx;
            if ((unsigned)gy < (unsigned)Himg && (unsigned)gx < (unsigned)Wimg)
                mv = mask[(size_t)n * Himg * Wimg + gy * Wimg + gx];
        }
        const int act = __syncthreads_or(mv > 0.5f);

        if (!act) {  // zero-fill the 14x14 block for all 64 couts
            for (int i = t; i < 64 * 14 * 7; i += TPB) {
                int co = i / 98, r2 = i - co * 98, y = r2 / 7, j = r2 - y * 7;
                float2* op = (float2*)(out +
                    (((size_t)n * 64 + co) * Himg + y0 + y) * Wimg + x0 + 2 * j);
                *op = make_float2(0.f, 0.f);
            }
            continue;
        }

        // stage X: threads 0..255 own pixel p=t (fp16, swizzled)
        if (t < 256) {
            const int p = t;
            const int ty = p >> 4, tx = p & 15;
            const int gy = y0 - 1 + ty, gx = x0 - 1 + tx;
            const bool inb =
                (unsigned)gy < (unsigned)Himg && (unsigned)gx < (unsigned)Wimg;
            const float* xp = x + (size_t)n * 64 * Himg * Wimg
                              + (size_t)gy * Wimg + gx;
            const int prow = p * 128, p7 = p & 7;
            #pragma unroll 4
            for (int c = 0; c < 64; c++) {
                float v = inb ? xp[(size_t)c * Himg * Wimg] : 0.f;
                uint32_t off = prow + ((((c >> 3) ^ p7) << 4)) + ((c & 7) << 1);
                *(uint16_t*)(smem + SM_X + off) =
                    __half_as_ushort(__float2half_rn(v));
            }
        }
        __syncthreads();

        // mainloop: 9 taps x 4 k-chunks (R12 config: tap rolled, kc unrolled)
        float acc[2][4][4];
        #pragma unroll
        for (int mt = 0; mt < 2; mt++)
            #pragma unroll
            for (int nt = 0; nt < 4; nt++)
                #pragma unroll
                for (int i = 0; i < 4; i++) acc[mt][nt][i] = 0.f;

        #pragma unroll 1
        for (int tap = 0; tap < 9; tap++) {
            const int ky = tap / 3;
            const int shift = ky * 16 + (tap - ky * 3);
            const uint32_t ab0 = abase_r + shift * 128;
            const int a70 = (ar + shift) & 7;
            const uint32_t wt = (uint32_t)SM_W + tap * 8192;
            #pragma unroll
            for (int kc = 0; kc < 4; kc++) {
                uint32_t ah[2][4], bh[8];
                const uint32_t ch = (((kc * 2 + ahi) ^ a70) << 4);
                ldsm4(ah[0], ab0 + ch);
                ldsm4(ah[1], ab0 + 16 * 128 + ch);
                const uint32_t bha = brow + wt + (((kc * 2 + bhi) ^ nx7) << 4);
                ldsm4(bh + 0, bha);
                ldsm4(bh + 4, bha + 2048);
                #pragma unroll
                for (int mt = 0; mt < 2; mt++)
                    #pragma unroll
                    for (int nt = 0; nt < 4; nt++)
                        mma_fp16(acc[mt][nt], ah[mt], bh + nt * 2);
            }
        }

        // epilogue: bias + masked stores (y = mblk*2+mt < 14 always)
        #pragma unroll
        for (int mt = 0; mt < 2; mt++) {
            const int y = mblk * 2 + mt;
            #pragma unroll
            for (int nt = 0; nt < 4; nt++) {
                const int nb = n0 + nt * 8 + 2 * tq;
                const float b0 = bias_s[nb], b1 = bias_s[nb + 1];
                float* base = out +
                    ((size_t)(n * 64 + nb) * Himg + (y0 + y)) * Wimg + x0;
                base[q] = acc[mt][nt][0] + b0;
                base[(size_t)Himg * Wimg + q] = acc[mt][nt][1] + b1;
                if (q < 6) {
                    base[q + 8] = acc[mt][nt][2] + b0;
                    base[(size_t)Himg * Wimg + q + 8] = acc[mt][nt][3] + b1;
                }
            }
        }
    }
}

extern "C" void kernel_launch(void* const* d_in, const int* in_sizes, int n_in,
                              void* d_out, int out_size) {
    const float* x      = (const float*)d_in[0];
    const float* mask   = (const float*)d_in[1];
    const float* weight = (const float*)d_in[2];
    const float* bias   = (const float*)d_in[3];
    float* out = (float*)d_out;

    wconv_kernel<<<(64 * 64 * 9 + 255) / 256, 256>>>(weight);

    cudaFuncSetAttribute(sbnet_mma_kernel,
                         cudaFuncAttributeMaxDynamicSharedMemorySize, SMEM_TOTAL);
    sbnet_mma_kernel<<<GRID, TPB, SMEM_TOTAL>>>(x, mask, bias, out);
}

// round 16
// speedup vs baseline: 1.4203x; 1.2589x over previous
#include <cuda_runtime.h>
#include <cuda_fp16.h>
#include <cstdint>

// SBNet block-sparse 3x3 conv via mma.sync (HMMA) pure-fp16 implicit GEMM.
// R15: R12 base (grid=4096, TPB=448, 2 CTAs/SM, rolled tap loop) + balanced
// staging: X staged by ALL 448 threads as half2 channel-pairs (STS.32),
// W copy on all threads after. Pure fp16 (fp32 accumulate).
// x[4][64][448][448] f32, mask[4][1][448][448], weight[64][64][3][3], bias[64],
// out[4][64][448][448]. 14x14 output blocks; active iff max(mask over 16x16
// gather window at offset -1) > 0.5.

namespace {
constexpr int Himg = 448, Wimg = 448, NBLK = 1024, TPB = 448;
constexpr int BS = 14;
constexpr int SM_X = 1024;             // [0..256) bias
constexpr int XB = 256 * 128;          // 256 pixel-rows x 64ch fp16
constexpr int SM_W = SM_X + XB;        // 33792
constexpr int WB = 9 * 64 * 128;       // 9 taps x 64 cout rows x 64 cin fp16
constexpr int SMEM_TOTAL = SM_W + WB;  // 107520
}

__device__ uint16_t g_w[9 * 64 * 64];

__device__ __forceinline__ uint32_t smem_u32(const void* p) {
    uint32_t a;
    asm("{ .reg .u64 t; cvta.to.shared.u64 t, %1; cvt.u32.u64 %0, t; }"
        : "=r"(a) : "l"(p));
    return a;
}
__device__ __forceinline__ void ldsm4(uint32_t* r, uint32_t addr) {
    asm volatile("ldmatrix.sync.aligned.m8n8.x4.shared.b16 {%0,%1,%2,%3}, [%4];"
                 : "=r"(r[0]), "=r"(r[1]), "=r"(r[2]), "=r"(r[3]) : "r"(addr));
}
__device__ __forceinline__ void mma_fp16(float* d, const uint32_t* a,
                                         const uint32_t* b) {
    asm volatile(
        "mma.sync.aligned.m16n8k16.row.col.f32.f16.f16.f32 "
        "{%0,%1,%2,%3},{%4,%5,%6,%7},{%8,%9},{%0,%1,%2,%3};"
        : "+f"(d[0]), "+f"(d[1]), "+f"(d[2]), "+f"(d[3])
        : "r"(a[0]), "r"(a[1]), "r"(a[2]), "r"(a[3]), "r"(b[0]), "r"(b[1]));
}

// one-time: weight[o][c][ky][kx] f32 -> swizzled fp16, layout
// [tap][o-row(128B)][cin], 16B-chunk swizzle: chunk ^= (o&7).
__global__ void wconv_kernel(const float* __restrict__ w) {
    int i = blockIdx.x * blockDim.x + threadIdx.x;
    if (i >= 64 * 64 * 9) return;
    int o = i / 576, r = i - o * 576, c = r / 9, k = r - c * 9;
    uint32_t off16 = k * 4096 + o * 64 + ((((c >> 3) ^ (o & 7)) << 3)) + (c & 7);
    g_w[off16] = __half_as_ushort(__float2half_rn(w[i]));
}

__global__ __launch_bounds__(TPB, 2)
void sbnet_mma_kernel(const float* __restrict__ x,
                      const float* __restrict__ mask,
                      const float* __restrict__ bias,
                      float* __restrict__ out) {
    extern __shared__ char smem[];
    const uint32_t sbase = smem_u32(smem);

    const int b   = blockIdx.x;
    const int n   = b >> 10;
    const int rem = b & (NBLK - 1);
    const int by  = rem >> 5, bx = rem & 31;
    const int t   = threadIdx.x;
    const int wid = t >> 5, lane = t & 31;
    const int y0  = by * BS, x0 = bx * BS;

    // ---- activity: threads 0..255 check the 16x16 gather window ----
    float mv = 0.f;
    if (t < 256) {
        int ty = t >> 4, tx = t & 15;
        int gy = y0 - 1 + ty, gx = x0 - 1 + tx;
        if ((unsigned)gy < (unsigned)Himg && (unsigned)gx < (unsigned)Wimg)
            mv = mask[(size_t)n * Himg * Wimg + gy * Wimg + gx];
    }
    const int act = __syncthreads_or(mv > 0.5f);

    if (!act) {  // zero-fill the 14x14 block for all 64 couts
        for (int i = t; i < 64 * 14 * 7; i += TPB) {
            int co = i / 98, r2 = i - co * 98, y = r2 / 7, j = r2 - y * 7;
            float2* op = (float2*)(out + (((size_t)n * 64 + co) * Himg + y0 + y) * Wimg
                                   + x0 + 2 * j);
            *op = make_float2(0.f, 0.f);
        }
        return;
    }

    // ---- staging: ALL threads stage X as half2 channel-pairs ----
    if (t < 64) *(float*)(smem + t * 4) = bias[t];
    {
        const float* xn = x + (size_t)n * 64 * Himg * Wimg;
        #pragma unroll 4
        for (int u = t; u < 8192; u += TPB) {      // u = cp*256 + p
            const int p = u & 255, c = (u >> 8) * 2;
            const int ty = p >> 4, tx = p & 15;
            const int gy = y0 - 1 + ty, gx = x0 - 1 + tx;
            float v0 = 0.f, v1 = 0.f;
            if ((unsigned)gy < (unsigned)Himg && (unsigned)gx < (unsigned)Wimg) {
                const float* xp = xn + (size_t)c * Himg * Wimg
                                  + (size_t)gy * Wimg + gx;
                v0 = xp[0];
                v1 = xp[(size_t)Himg * Wimg];
            }
            const __half2 h = __floats2half2_rn(v0, v1);
            const uint32_t off =
                p * 128 + ((((c >> 3) ^ (p & 7)) << 4)) + ((c & 7) << 1);
            *(uint32_t*)(smem + SM_X + off) = *(const uint32_t*)&h;
        }
    }
    // ---- W copy: all threads (independent of X stores, overlaps LDGs) ----
    {
        const uint4* sw = (const uint4*)g_w;
        uint4* dw = (uint4*)(smem + SM_W);
        #pragma unroll 2
        for (int i = t; i < WB / 16; i += TPB) dw[i] = sw[i];
    }
    __syncthreads();

    // ---- compute: warp = (mblk 0..6) x (nhalf 0..1); tile M=32, N=32 ----
    const int nhalf = wid / 7;
    const int mblk  = wid - nhalf * 7;
    const int m0 = mblk * 32;              // pixel rows (all valid y<14)
    const int n0 = nhalf * 32;             // cout block
    const int q  = lane >> 2, tq = lane & 3;

    float acc[2][4][4];
    #pragma unroll
    for (int mt = 0; mt < 2; mt++)
        #pragma unroll
        for (int nt = 0; nt < 4; nt++)
            #pragma unroll
            for (int i = 0; i < 4; i++) acc[mt][nt][i] = 0.f;

    // per-lane invariants
    const int arow_l = (lane & 15);        // A: row within m16 tile
    const int ahi    = lane >> 4;          // A: k 16B-chunk select
    const int nrow   = n0 + (lane & 7) + ((lane & 16) >> 1);  // B row (cout)
    const int bhi    = (lane >> 3) & 1;    // B: k 16B-chunk select
    const uint32_t brow = sbase + nrow * 128;  // (nrow+16)&7 == nrow&7
    const int nx7 = nrow & 7;
    const int ar = m0 + arow_l;
    const uint32_t abase_r = sbase + (uint32_t)SM_X + ar * 128;

    #pragma unroll 1
    for (int tap = 0; tap < 9; tap++) {
        const int ky = tap / 3;
        const int shift = ky * 16 + (tap - ky * 3);
        const uint32_t ab0 = abase_r + shift * 128;
        const int a70 = (ar + shift) & 7;
        const uint32_t wt = (uint32_t)SM_W + tap * 8192;
        #pragma unroll
        for (int kc = 0; kc < 4; kc++) {
            uint32_t ah[2][4], bh[8];
            const uint32_t ch = (((kc * 2 + ahi) ^ a70) << 4);
            ldsm4(ah[0], ab0 + ch);
            ldsm4(ah[1], ab0 + 16 * 128 + ch);
            const uint32_t bha = brow + wt + (((kc * 2 + bhi) ^ nx7) << 4);
            ldsm4(bh + 0, bha);
            ldsm4(bh + 4, bha + 2048);
            // 8 independent MMAs (distinct accumulators)
            #pragma unroll
            for (int mt = 0; mt < 2; mt++)
                #pragma unroll
                for (int nt = 0; nt < 4; nt++)
                    mma_fp16(acc[mt][nt], ah[mt], bh + nt * 2);
        }
    }

    // ---- epilogue: bias + masked stores (y = mblk*2+mt < 14 always) ----
    const float* bias_s = (const float*)smem;
    #pragma unroll
    for (int mt = 0; mt < 2; mt++) {
        const int y = mblk * 2 + mt;
        #pragma unroll
        for (int nt = 0; nt < 4; nt++) {
            const int nb = n0 + nt * 8 + 2 * tq;
            const float b0 = bias_s[nb], b1 = bias_s[nb + 1];
            float* base = out + ((size_t)(n * 64 + nb) * Himg + (y0 + y)) * Wimg + x0;
            base[q] = acc[mt][nt][0] + b0;
            base[(size_t)Himg * Wimg + q] = acc[mt][nt][1] + b1;
            if (q < 6) {
                base[q + 8] = acc[mt][nt][2] + b0;
                base[(size_t)Himg * Wimg + q + 8] = acc[mt][nt][3] + b1;
            }
        }
    }
}

extern "C" void kernel_launch(void* const* d_in, const int* in_sizes, int n_in,
                              void* d_out, int out_size) {
    const float* x      = (const float*)d_in[0];
    const float* mask   = (const float*)d_in[1];
    const float* weight = (const float*)d_in[2];
    const float* bias   = (const float*)d_in[3];
    float* out = (float*)d_out;

    wconv_kernel<<<(64 * 64 * 9 + 255) / 256, 256>>>(weight);

    cudaFuncSetAttribute(sbnet_mma_kernel,
                         cudaFuncAttributeMaxDynamicSharedMemorySize, SMEM_TOTAL);
    sbnet_mma_kernel<<<4 * NBLK, TPB, SMEM_TOTAL>>>(x, mask, bias, out);
}